// round 6
// baseline (speedup 1.0000x reference)
#include <cuda_runtime.h>
#include <cuda_bf16.h>
#include <cstdint>

#define EPS   1e-5f
#define NB    8
#define NC    256
#define HW    16384
#define CHW   (NC * HW)

typedef unsigned int       u32;
typedef unsigned long long u64;
typedef unsigned short     u16;

// ---------------- device scratch (allocation-free) ----------------
__device__ float         g_sum  [NB * NC];
__device__ float         g_sumsq[NB * NC];
__device__ __nv_bfloat16 g_Ah[NB * NC * NC];   // folded matrix, bf16 hi (1 MB)
__device__ __nv_bfloat16 g_Al[NB * NC * NC];   // folded matrix, bf16 lo (1 MB)
__device__ float         g_E [NB * NC];

// ---------------- helpers ----------------
__device__ __forceinline__ u32 smem_u32(const void* p) {
    u32 a;
    asm("{ .reg .u64 t; cvta.to.shared.u64 t, %1; cvt.u32.u64 %0, t; }" : "=r"(a) : "l"(p));
    return a;
}
__device__ __forceinline__ void split_bf16(float f, u16& h, u16& l) {
    __nv_bfloat16 hb = __float2bfloat16(f);
    float fh = __bfloat162float(hb);
    __nv_bfloat16 lb = __float2bfloat16(f - fh);
    h = *(u16*)&hb;
    l = *(u16*)&lb;
}

#define LDMX4(r, addr) \
    asm volatile("ldmatrix.sync.aligned.m8n8.x4.shared.b16 {%0,%1,%2,%3}, [%4];" \
        : "=r"((r)[0]), "=r"((r)[1]), "=r"((r)[2]), "=r"((r)[3]) : "r"(addr))
#define LDMX4T(r, addr) \
    asm volatile("ldmatrix.sync.aligned.m8n8.x4.trans.shared.b16 {%0,%1,%2,%3}, [%4];" \
        : "=r"((r)[0]), "=r"((r)[1]), "=r"((r)[2]), "=r"((r)[3]) : "r"(addr))
#define MMA16816(c, a, b0, b1) \
    asm volatile("mma.sync.aligned.m16n8k16.row.col.f32.bf16.bf16.f32 " \
        "{%0,%1,%2,%3}, {%4,%5,%6,%7}, {%8,%9}, {%0,%1,%2,%3};" \
        : "+f"((c)[0]), "+f"((c)[1]), "+f"((c)[2]), "+f"((c)[3]) \
        : "r"((a)[0]), "r"((a)[1]), "r"((a)[2]), "r"((a)[3]), "r"(b0), "r"(b1))
#define CP_ASYNC16(smem_addr, gptr) \
    asm volatile("cp.async.cg.shared.global [%0], [%1], 16;" \
        :: "r"(smem_addr), "l"(gptr) : "memory")
#define CP_COMMIT() asm volatile("cp.async.commit_group;" ::: "memory")
#define CP_WAIT0()  asm volatile("cp.async.wait_group 0;" ::: "memory")

// ========================================================================
// Kernel 1: per-(b,c) sum / sumsq over H*W   (measured 24us, 70% HBM)
// ========================================================================
__global__ __launch_bounds__(256) void stats_kernel(const float* __restrict__ x) {
    int bc = blockIdx.x;
    const float4* xv = (const float4*)(x + (size_t)bc * HW);
    float s = 0.f, q = 0.f;
    #pragma unroll
    for (int j = 0; j < 16; j++) {
        float4 v = xv[threadIdx.x + j * 256];
        s += v.x + v.y + v.z + v.w;
        q += v.x * v.x + v.y * v.y + v.z * v.z + v.w * v.w;
    }
    #pragma unroll
    for (int off = 16; off; off >>= 1) {
        s += __shfl_xor_sync(0xffffffffu, s, off);
        q += __shfl_xor_sync(0xffffffffu, q, off);
    }
    __shared__ float ss[8], sq[8];
    int w = threadIdx.x >> 5, l = threadIdx.x & 31;
    if (l == 0) { ss[w] = s; sq[w] = q; }
    __syncthreads();
    if (threadIdx.x == 0) {
        float S = 0.f, Q = 0.f;
        #pragma unroll
        for (int i = 0; i < 8; i++) { S += ss[i]; Q += sq[i]; }
        g_sum[bc] = S;
        g_sumsq[bc] = Q;
    }
}

// ========================================================================
// Kernel 2: fold stats + gamma/beta into Ah/Al (bf16 row-major) and E
// ========================================================================
__global__ __launch_bounds__(256) void prep_kernel(const float* __restrict__ params,
                                                   const float* __restrict__ W) {
    int b = blockIdx.x;
    int o = threadIdx.x;

    __shared__ float sm[NC], sr[NC];
    __shared__ float redS[8], redQ[8];
    __shared__ float sMR[2];

    float s = g_sum[b * NC + o];
    float q = g_sumsq[b * NC + o];
    float m   = s * (1.f / (float)HW);
    float var = q * (1.f / (float)HW) - m * m;
    sm[o] = m;
    sr[o] = rsqrtf(var + EPS);

    float rs = s, rq = q;
    #pragma unroll
    for (int off = 16; off; off >>= 1) {
        rs += __shfl_xor_sync(0xffffffffu, rs, off);
        rq += __shfl_xor_sync(0xffffffffu, rq, off);
    }
    int w = o >> 5, l = o & 31;
    if (l == 0) { redS[w] = rs; redQ[w] = rq; }
    __syncthreads();
    if (o == 0) {
        float S = 0.f, Q = 0.f;
        #pragma unroll
        for (int i = 0; i < 8; i++) { S += redS[i]; Q += redQ[i]; }
        float M = S * (1.f / (float)CHW);
        float V = Q * (1.f / (float)CHW) - M * M;
        sMR[0] = M;
        sMR[1] = rsqrtf(V + EPS);
    }
    __syncthreads();
    float M = sMR[0], R = sMR[1];

    float gamma = params[b * 2 * NC + o];
    float beta  = params[b * 2 * NC + NC + o];
    const float* Wrow = W + o * 2 * NC;
    __nv_bfloat16* ah = g_Ah + (size_t)(b * NC + o) * NC;
    __nv_bfloat16* al = g_Al + (size_t)(b * NC + o) * NC;

    float d = 0.f, w2s = 0.f;
    for (int i = 0; i < NC; i++) {
        float w1 = Wrow[i];
        float w2 = Wrow[NC + i];
        float ri = sr[i];
        float a  = gamma * (w1 * ri + R * w2);
        u16 h, lo;
        split_bf16(a, h, lo);
        ah[i] = *(__nv_bfloat16*)&h;
        al[i] = *(__nv_bfloat16*)&lo;
        d   += w1 * ri * sm[i];
        w2s += w2;
    }
    g_E[b * NC + o] = beta - gamma * (d + R * M * w2s);
}

// ========================================================================
// Kernel 3: HMMA GEMM  out[b][o][p] = sum_k A[b][o][k] x[b][k][p] + E
// CTA: 128(o) x 64(p), K chunks of 32. 256 threads = 8 warps (2M x 4N).
// A hi/lo via cp.async (no staging regs); X converted in-register.
// Register-lean inner loop: B frags resident, A frags reloaded per mt.
// ========================================================================
#define BK      32
#define A_PITCH 80      // bytes (64B data + 16B pad): conflict-free ldmatrix
#define X_PITCH 144     // bytes (128B data + 16B pad)
#define BUF_STRIDE 30720

__global__ __launch_bounds__(256, 2) void gemm_kernel(const float* __restrict__ x,
                                                      float* __restrict__ out) {
    extern __shared__ __align__(16) char smem[];
    const u32 sb = smem_u32(smem);

    const int tid = threadIdx.x, lane = tid & 31, wid = tid >> 5;
    const int warp_m = wid >> 2;       // 0..1  -> 64 rows each
    const int warp_n = wid & 3;        // 0..3  -> 16 cols each
    const int oT = blockIdx.x * 128;   // gridDim.x = 2 (fastest: L2 reuse of x)
    const int pT = blockIdx.y * 64;    // gridDim.y = 256
    const int b  = blockIdx.z;

    const __nv_bfloat16* gAh = g_Ah + (size_t)(b * NC + oT) * NC;
    const __nv_bfloat16* gAl = g_Al + (size_t)(b * NC + oT) * NC;
    const float*         gX  = x + (size_t)b * NC * HW + pT;

    // A: 128 rows x 4 x 16B units = 512; this thread does units tid, tid+256
    const int ar0 = tid >> 2,        ac = tid & 3;
    const int ar1 = (tid + 256) >> 2;
    // X: 32 rows x 16 float4 = 512 units
    const int xk0 = tid >> 4,        xp = tid & 15;
    const int xk1 = (tid + 256) >> 4;

    // issue cp.async for A chunk kc into buffer buf
    #define ASYNC_A(kc, bufb) do { \
        u32 AH_ = (bufb), AL_ = (bufb) + 10240; \
        CP_ASYNC16(AH_ + (u32)ar0 * A_PITCH + (u32)ac * 16, gAh + (size_t)ar0 * NC + (kc) * BK + ac * 8); \
        CP_ASYNC16(AH_ + (u32)ar1 * A_PITCH + (u32)ac * 16, gAh + (size_t)ar1 * NC + (kc) * BK + ac * 8); \
        CP_ASYNC16(AL_ + (u32)ar0 * A_PITCH + (u32)ac * 16, gAl + (size_t)ar0 * NC + (kc) * BK + ac * 8); \
        CP_ASYNC16(AL_ + (u32)ar1 * A_PITCH + (u32)ac * 16, gAl + (size_t)ar1 * NC + (kc) * BK + ac * 8); \
        CP_COMMIT(); \
    } while (0)

    float4 px0, px1;
    #define LOAD_X(kc) do { \
        px0 = *(const float4*)(gX + (size_t)((kc) * BK + xk0) * HW + xp * 4); \
        px1 = *(const float4*)(gX + (size_t)((kc) * BK + xk1) * HW + xp * 4); \
    } while (0)

    // convert + store X into buffer
    #define STORE_X(bufb) do { \
        u32 XH_ = (bufb) + 20480, XL_ = (bufb) + 25088; \
        const float4 pxs[2] = { px0, px1 }; \
        const int    xks[2] = { xk0, xk1 }; \
        _Pragma("unroll") \
        for (int u = 0; u < 2; u++) { \
            u16 h[4], l[4]; \
            split_bf16(pxs[u].x, h[0], l[0]); \
            split_bf16(pxs[u].y, h[1], l[1]); \
            split_bf16(pxs[u].z, h[2], l[2]); \
            split_bf16(pxs[u].w, h[3], l[3]); \
            u32 h01 = (u32)h[0] | ((u32)h[1] << 16); \
            u32 h23 = (u32)h[2] | ((u32)h[3] << 16); \
            u32 l01 = (u32)l[0] | ((u32)l[1] << 16); \
            u32 l23 = (u32)l[2] | ((u32)l[3] << 16); \
            u32 xh = XH_ + (u32)xks[u] * X_PITCH + (u32)xp * 8; \
            u32 xl = XL_ + (u32)xks[u] * X_PITCH + (u32)xp * 8; \
            asm volatile("st.shared.v2.b32 [%0], {%1,%2};" :: "r"(xh), "r"(h01), "r"(h23) : "memory"); \
            asm volatile("st.shared.v2.b32 [%0], {%1,%2};" :: "r"(xl), "r"(l01), "r"(l23) : "memory"); \
        } \
    } while (0)

    float acc[4][2][4];
    #pragma unroll
    for (int i = 0; i < 4; i++)
        #pragma unroll
        for (int j = 0; j < 2; j++)
            #pragma unroll
            for (int v = 0; v < 4; v++) acc[i][j][v] = 0.f;

    // prologue
    ASYNC_A(0, sb);
    LOAD_X(0);

    for (int kc = 0; kc < NC / BK; kc++) {
        const u32 bufb = sb + (u32)(kc & 1) * BUF_STRIDE;

        STORE_X(bufb);
        CP_WAIT0();                 // A(kc) resident
        __syncthreads();

        if (kc < NC / BK - 1) {
            const u32 nbuf = sb + (u32)((kc + 1) & 1) * BUF_STRIDE;
            ASYNC_A(kc + 1, nbuf);
            LOAD_X(kc + 1);
        }

        const u32 AH = bufb, AL = bufb + 10240, XH = bufb + 20480, XL = bufb + 25088;
        const u32 aRow  = (u32)(warp_m * 64 + (lane & 15)) * A_PITCH + (u32)(lane >> 4) * 16;
        const u32 xBase = (u32)(lane & 15) * X_PITCH + (u32)(lane >> 4) * 16 + (u32)warp_n * 32;

        #pragma unroll
        for (int ks = 0; ks < 2; ks++) {
            u32 bh[4], bl[4];
            LDMX4T(bh, XH + xBase + (u32)ks * (16 * X_PITCH));
            LDMX4T(bl, XL + xBase + (u32)ks * (16 * X_PITCH));
            #pragma unroll
            for (int mt = 0; mt < 4; mt++) {
                u32 ah[4], al[4];
                LDMX4(ah, AH + aRow + (u32)mt * (16 * A_PITCH) + (u32)ks * 32);
                LDMX4(al, AL + aRow + (u32)mt * (16 * A_PITCH) + (u32)ks * 32);
                #pragma unroll
                for (int nt = 0; nt < 2; nt++) {
                    MMA16816(acc[mt][nt], ah, bh[nt * 2], bh[nt * 2 + 1]);
                    MMA16816(acc[mt][nt], ah, bl[nt * 2], bl[nt * 2 + 1]);
                    MMA16816(acc[mt][nt], al, bh[nt * 2], bh[nt * 2 + 1]);
                }
            }
        }
        __syncthreads();            // all reads of this buffer done before it is refilled
    }

    // ---- epilogue: add folded bias, write fp32 ----
    #pragma unroll
    for (int mt = 0; mt < 4; mt++) {
        int r = oT + warp_m * 64 + mt * 16 + (lane >> 2);
        float e0 = g_E[b * NC + r];
        float e1 = g_E[b * NC + r + 8];
        float* o0 = out + (size_t)(b * NC + r) * HW + pT + warp_n * 16 + (lane & 3) * 2;
        float* o1 = o0 + (size_t)8 * HW;
        #pragma unroll
        for (int nt = 0; nt < 2; nt++) {
            float2 v0 = { acc[mt][nt][0] + e0, acc[mt][nt][1] + e0 };
            float2 v1 = { acc[mt][nt][2] + e1, acc[mt][nt][3] + e1 };
            *(float2*)(o0 + nt * 8) = v0;
            *(float2*)(o1 + nt * 8) = v1;
        }
    }
}

// ========================================================================
extern "C" void kernel_launch(void* const* d_in, const int* in_sizes, int n_in,
                              void* d_out, int out_size) {
    const float* x      = (const float*)d_in[0];
    const float* params = (const float*)d_in[1];
    const float* W      = (const float*)d_in[2];
    float* out          = (float*)d_out;

    const int SMEM_BYTES = 2 * BUF_STRIDE;   // 60 KB
    cudaFuncSetAttribute(gemm_kernel, cudaFuncAttributeMaxDynamicSharedMemorySize, SMEM_BYTES);

    stats_kernel<<<NB * NC, 256>>>(x);
    prep_kernel<<<NB, 256>>>(params, W);
    dim3 grid(2, 256, NB);
    gemm_kernel<<<grid, 256, SMEM_BYTES>>>(x, out);
}